// round 1
// baseline (speedup 1.0000x reference)
#include <cuda_runtime.h>

#define B_ 256
#define N_ 64
#define T_ 4096
#define H_ 16

typedef unsigned long long ull;

// scratch for per-(b,n) variance
__device__ float g_energy[B_ * N_];

static __device__ __forceinline__ ull packf2(float x, float y) {
    ull r;
    asm("mov.b64 %0, {%1,%2};" : "=l"(r) : "f"(x), "f"(y));
    return r;
}
static __device__ __forceinline__ void unpackf2(ull v, float& x, float& y) {
    asm("mov.b64 {%0,%1}, %2;" : "=f"(x), "=f"(y) : "l"(v));
}
static __device__ __forceinline__ ull ffma2(ull a, ull b, ull c) {
    ull d;
    asm("fma.rn.f32x2 %0, %1, %2, %3;" : "=l"(d) : "l"(a), "l"(b), "l"(c));
    return d;
}

// K1: energy[b,n] = var over T of x[b,n,:]. One block per (b,n).
__global__ void __launch_bounds__(256) k_var(const float* __restrict__ x) {
    size_t base = (size_t)blockIdx.x * T_;
    const float4* xp = (const float4*)(x + base);
    float s = 0.f, ss = 0.f;
#pragma unroll
    for (int it = 0; it < 4; it++) {
        float4 v = xp[threadIdx.x + it * 256];
        s  += (v.x + v.y) + (v.z + v.w);
        ss += (v.x * v.x + v.y * v.y) + (v.z * v.z + v.w * v.w);
    }
#pragma unroll
    for (int o = 16; o; o >>= 1) {
        s  += __shfl_xor_sync(0xffffffffu, s, o);
        ss += __shfl_xor_sync(0xffffffffu, ss, o);
    }
    __shared__ float sh_s[8], sh_ss[8];
    if ((threadIdx.x & 31) == 0) {
        sh_s[threadIdx.x >> 5] = s;
        sh_ss[threadIdx.x >> 5] = ss;
    }
    __syncthreads();
    if (threadIdx.x == 0) {
        float S = 0.f, SS = 0.f;
#pragma unroll
        for (int w = 0; w < 8; w++) { S += sh_s[w]; SS += sh_ss[w]; }
        float mean = S * (1.f / T_);
        g_energy[blockIdx.x] = SS * (1.f / T_) - mean * mean;
    }
}

// K2: closed-form logits + masked softmax. One block per batch, thread i = row i.
__global__ void __launch_bounds__(64) k_attn(const float* __restrict__ Wq,
                                             const float* __restrict__ bq,
                                             const float* __restrict__ Wk,
                                             const float* __restrict__ bk,
                                             float* __restrict__ attnw) {
    int b = blockIdx.x;
    int i = threadIdx.x;
    __shared__ float es[N_];
    es[i] = g_energy[b * N_ + i];

    float cqk = 0.f, cqb = 0.f, cbk = 0.f, cbb = 0.f;
#pragma unroll
    for (int h = 0; h < H_; h++) {
        float wq = Wq[h], wk = Wk[h], vq = bq[h], vk = bk[h];
        cqk += wq * wk;
        cqb += wq * vk;
        cbk += vq * wk;
        cbb += vq * vk;
    }
    __syncthreads();

    const float scale = 0.25f;  // H^-0.5
    float ei = es[i];
    float l[N_];
    float m = -3.4e38f;
#pragma unroll
    for (int j = 0; j < N_; j++) {
        float ej = es[j];
        float v = scale * (cqk * ei * ej + cqb * ei + cbk * ej + cbb);
        if (j == i) v = -1e9f;
        l[j] = v;
        m = fmaxf(m, v);
    }
    float sum = 0.f;
#pragma unroll
    for (int j = 0; j < N_; j++) {
        float e = expf(l[j] - m);
        l[j] = e;
        sum += e;
    }
    float inv = 1.f / sum;
    float* outp = attnw + ((size_t)b * N_ + i) * N_;
#pragma unroll
    for (int j = 0; j < N_; j += 4) {
        float4 v = make_float4(l[j] * inv, l[j + 1] * inv, l[j + 2] * inv, l[j + 3] * inv);
        *(float4*)(outp + j) = v;
    }
}

// K3: out[b,i,t] = x[b,i,t] + sum_j attnw[b,i,j] * x[b,j,t]
// Block = (t-tile of 128, batch b). 256 threads; thread computes 8 i-rows x 4 t-cols
// using packed f32x2 FMAs (2 t's per instruction). attn_w is staged in shared
// PRE-DUPLICATED as (a,a) float2 so the inner loop has zero pack MOVs.
__global__ void __launch_bounds__(256, 3) k_out(const float* __restrict__ x,
                                                const float* __restrict__ attnw,
                                                float* __restrict__ out) {
    extern __shared__ float smem[];
    float2* As2 = (float2*)smem;            // [64*64] duplicated A  (32 KB)
    float*  xs  = smem + 64 * 64 * 2;       // [64][128] x tile      (32 KB)

    int b  = blockIdx.y;
    int t0 = blockIdx.x * 128;
    const float* xb = x + (size_t)b * (N_ * T_);
    const float* ab = attnw + (size_t)b * (N_ * N_);

    // stage A, duplicated
#pragma unroll
    for (int s4 = 0; s4 < 4; s4++) {
        int e4 = threadIdx.x + s4 * 256;            // float4 index 0..1023
        float4 a = ((const float4*)ab)[e4];
        float2* d = As2 + e4 * 4;
        d[0] = make_float2(a.x, a.x);
        d[1] = make_float2(a.y, a.y);
        d[2] = make_float2(a.z, a.z);
        d[3] = make_float2(a.w, a.w);
    }
    // stage x tile [64 rows][128 t]
#pragma unroll
    for (int s4 = 0; s4 < 8; s4++) {
        int idx = threadIdx.x + s4 * 256;           // float4 index 0..2047
        int j = idx >> 5, c = idx & 31;
        float4 v = *(const float4*)(xb + (size_t)j * T_ + (t0 + c * 4));
        *(float4*)(xs + j * 128 + c * 4) = v;
    }
    __syncthreads();

    int ix = threadIdx.x & 31;   // t-group: t = t0 + ix*4 .. +3
    int iy = threadIdx.x >> 5;   // i-group: i = iy*8 .. +7
    int i0 = iy * 8;
    int p0 = ix * 2;             // float2 column index within row

    const ull* xs2 = (const ull*)xs;   // [64][64] f32x2
    const ull* A2  = (const ull*)As2;  // [64][64] duplicated pairs

    ull acc[8][2];
    // init with residual x[b, i0+r, t...]
#pragma unroll
    for (int r = 0; r < 8; r++) {
        float4 xi = *(const float4*)(xs + (i0 + r) * 128 + ix * 4);
        acc[r][0] = packf2(xi.x, xi.y);
        acc[r][1] = packf2(xi.z, xi.w);
    }

#pragma unroll 4
    for (int k = 0; k < 64; k++) {
        ulonglong2 xv = *(const ulonglong2*)(xs2 + k * 64 + p0);  // LDS.128: two f32x2
#pragma unroll
        for (int r = 0; r < 8; r++) {
            ull a = A2[(i0 + r) * 64 + k];                        // LDS.64 broadcast
            acc[r][0] = ffma2(a, xv.x, acc[r][0]);
            acc[r][1] = ffma2(a, xv.y, acc[r][1]);
        }
    }

    float* ob = out + (size_t)b * (N_ * T_) + t0 + ix * 4;
#pragma unroll
    for (int r = 0; r < 8; r++) {
        float4 v;
        unpackf2(acc[r][0], v.x, v.y);
        unpackf2(acc[r][1], v.z, v.w);
        *(float4*)(ob + (size_t)(i0 + r) * T_) = v;
    }
}

extern "C" void kernel_launch(void* const* d_in, const int* in_sizes, int n_in,
                              void* d_out, int out_size) {
    const float* x  = (const float*)d_in[0];
    const float* Wq = (const float*)d_in[1];
    const float* bq = (const float*)d_in[2];
    const float* Wk = (const float*)d_in[3];
    const float* bk = (const float*)d_in[4];

    float* out   = (float*)d_out;                       // [B,N,T,1]
    float* attnw = out + (size_t)B_ * N_ * T_;          // [B,N,N] (second tuple element)

    cudaFuncSetAttribute(k_out, cudaFuncAttributeMaxDynamicSharedMemorySize, 65536);

    k_var<<<B_ * N_, 256>>>(x);
    k_attn<<<B_, 64>>>(Wq, bq, Wk, bk, attnw);
    k_out<<<dim3(T_ / 128, B_), 256, 65536>>>(x, attnw, out);
}

// round 2
// speedup vs baseline: 1.4432x; 1.4432x over previous
#include <cuda_runtime.h>

#define B_ 256
#define N_ 64
#define T_ 4096
#define H_ 16

typedef unsigned long long ull;

__device__ float g_energy[B_ * N_];

static __device__ __forceinline__ ull packf2(float x, float y) {
    ull r;
    asm("mov.b64 %0, {%1,%2};" : "=l"(r) : "f"(x), "f"(y));
    return r;
}
static __device__ __forceinline__ void unpackf2(ull v, float& x, float& y) {
    asm("mov.b64 {%0,%1}, %2;" : "=f"(x), "=f"(y) : "l"(v));
}
static __device__ __forceinline__ ull ffma2(ull a, ull b, ull c) {
    ull d;
    asm("fma.rn.f32x2 %0, %1, %2, %3;" : "=l"(d) : "l"(a), "l"(b), "l"(c));
    return d;
}

// K1: energy[b,n] = var over T of x[b,n,:]. One block per (b,n). DRAM-bound, ~at roofline.
__global__ void __launch_bounds__(256) k_var(const float* __restrict__ x) {
    size_t base = (size_t)blockIdx.x * T_;
    const float4* xp = (const float4*)(x + base);
    float s = 0.f, ss = 0.f;
#pragma unroll
    for (int it = 0; it < 4; it++) {
        float4 v = xp[threadIdx.x + it * 256];
        s  += (v.x + v.y) + (v.z + v.w);
        ss += (v.x * v.x + v.y * v.y) + (v.z * v.z + v.w * v.w);
    }
#pragma unroll
    for (int o = 16; o; o >>= 1) {
        s  += __shfl_xor_sync(0xffffffffu, s, o);
        ss += __shfl_xor_sync(0xffffffffu, ss, o);
    }
    __shared__ float sh_s[8], sh_ss[8];
    if ((threadIdx.x & 31) == 0) {
        sh_s[threadIdx.x >> 5] = s;
        sh_ss[threadIdx.x >> 5] = ss;
    }
    __syncthreads();
    if (threadIdx.x == 0) {
        float S = 0.f, SS = 0.f;
#pragma unroll
        for (int w = 0; w < 8; w++) { S += sh_s[w]; SS += sh_ss[w]; }
        float mean = S * (1.f / T_);
        g_energy[blockIdx.x] = SS * (1.f / T_) - mean * mean;
    }
}

// K2: closed-form logits + masked softmax. One block per batch, thread i = row i.
__global__ void __launch_bounds__(64) k_attn(const float* __restrict__ Wq,
                                             const float* __restrict__ bq,
                                             const float* __restrict__ Wk,
                                             const float* __restrict__ bk,
                                             float* __restrict__ attnw) {
    int b = blockIdx.x;
    int i = threadIdx.x;
    __shared__ float es[N_];
    es[i] = g_energy[b * N_ + i];

    float cqk = 0.f, cqb = 0.f, cbk = 0.f, cbb = 0.f;
#pragma unroll
    for (int h = 0; h < H_; h++) {
        float wq = Wq[h], wk = Wk[h], vq = bq[h], vk = bk[h];
        cqk += wq * wk;
        cqb += wq * vk;
        cbk += vq * wk;
        cbb += vq * vk;
    }
    __syncthreads();

    const float scale = 0.25f;  // H^-0.5
    float ei = es[i];
    float l[N_];
    float m = -3.4e38f;
#pragma unroll
    for (int j = 0; j < N_; j++) {
        float ej = es[j];
        float v = scale * (cqk * ei * ej + cqb * ei + cbk * ej + cbb);
        if (j == i) v = -1e9f;
        l[j] = v;
        m = fmaxf(m, v);
    }
    float sum = 0.f;
#pragma unroll
    for (int j = 0; j < N_; j++) {
        float e = expf(l[j] - m);
        l[j] = e;
        sum += e;
    }
    float inv = 1.f / sum;
    float* outp = attnw + ((size_t)b * N_ + i) * N_;
#pragma unroll
    for (int j = 0; j < N_; j += 4) {
        float4 v = make_float4(l[j] * inv, l[j + 1] * inv, l[j + 2] * inv, l[j + 3] * inv);
        *(float4*)(outp + j) = v;
    }
}

// K3: out[b,i,t] = x[b,i,t] + sum_j attnw[b,i,j] * x[b,j,t]
// Block = (128-t tile, batch). 256 threads. Thread: 8 i-rows x 2 pair-cols (4 t).
// Inner body processes TWO k-steps: one broadcast LDS.128 per row serves both k's
// (A stored pre-duplicated as (a,a) f32x2 pairs, so A[i][k],A[i][k+1] are 16
// contiguous bytes). x pairs loaded as conflict-free LDS.64. Per warp per 2k:
// 16 crossbar wavefronts vs 32 FFMA2 = 16 SM-fma-cycles -> fma/crossbar balanced.
__global__ void __launch_bounds__(256, 2) k_out(const float* __restrict__ x,
                                                const float* __restrict__ attnw,
                                                float* __restrict__ out) {
    extern __shared__ float smem[];
    ull*   A2   = (ull*)smem;               // [64][64] duplicated A pairs (32 KB)
    float* xs   = smem + 64 * 64 * 2;       // [64][128] x tile            (32 KB)
    ull*   xs_u = (ull*)xs;                 // [64][64] pairs

    int b  = blockIdx.y;
    int t0 = blockIdx.x * 128;
    const float* xb = x + (size_t)b * (N_ * T_);
    const float* ab = attnw + (size_t)b * (N_ * N_);

    // stage A, duplicated as (a,a) pairs
#pragma unroll
    for (int s4 = 0; s4 < 4; s4++) {
        int e4 = threadIdx.x + s4 * 256;            // float4 index 0..1023
        float4 a = ((const float4*)ab)[e4];
        ull* d = A2 + e4 * 4;
        d[0] = packf2(a.x, a.x);
        d[1] = packf2(a.y, a.y);
        d[2] = packf2(a.z, a.z);
        d[3] = packf2(a.w, a.w);
    }
    // stage x tile [64 rows][128 t]
#pragma unroll
    for (int s4 = 0; s4 < 8; s4++) {
        int idx = threadIdx.x + s4 * 256;           // float4 index 0..2047
        int j = idx >> 5, c = idx & 31;
        float4 v = *(const float4*)(xb + (size_t)j * T_ + (t0 + c * 4));
        *(float4*)(xs + j * 128 + c * 4) = v;
    }
    __syncthreads();

    int ix = threadIdx.x & 31;   // pair column c0: cols {ix, ix+32}
    int iy = threadIdx.x >> 5;   // warp -> i-group
    int i0 = iy * 8;

    ull acc[8][2];
    // init with residual x[b, i0+r, t...] (LDS.64 conflict-free)
#pragma unroll
    for (int r = 0; r < 8; r++) {
        acc[r][0] = xs_u[(i0 + r) * 64 + ix];
        acc[r][1] = xs_u[(i0 + r) * 64 + ix + 32];
    }

    const ull* arow = A2 + i0 * 64;
#pragma unroll 2
    for (int k = 0; k < 64; k += 2) {
        // x pairs for the two k-steps (conflict-free LDS.64)
        ull xv00 = xs_u[k * 64 + ix];
        ull xv01 = xs_u[k * 64 + ix + 32];
        ull xv10 = xs_u[(k + 1) * 64 + ix];
        ull xv11 = xs_u[(k + 1) * 64 + ix + 32];
#pragma unroll
        for (int r = 0; r < 8; r++) {
            // one broadcast LDS.128 = duplicated A for k and k+1 of row r
            ulonglong2 a2 = *(const ulonglong2*)(arow + r * 64 + k);
            acc[r][0] = ffma2(a2.x, xv00, acc[r][0]);
            acc[r][1] = ffma2(a2.x, xv01, acc[r][1]);
            acc[r][0] = ffma2(a2.y, xv10, acc[r][0]);
            acc[r][1] = ffma2(a2.y, xv11, acc[r][1]);
        }
    }

    float* ob = out + (size_t)b * (N_ * T_) + t0;
#pragma unroll
    for (int r = 0; r < 8; r++) {
        float2 v0, v1;
        unpackf2(acc[r][0], v0.x, v0.y);
        unpackf2(acc[r][1], v1.x, v1.y);
        float* orow = ob + (size_t)(i0 + r) * T_;
        *(float2*)(orow + ix * 2)      = v0;
        *(float2*)(orow + 64 + ix * 2) = v1;
    }
}

extern "C" void kernel_launch(void* const* d_in, const int* in_sizes, int n_in,
                              void* d_out, int out_size) {
    const float* x  = (const float*)d_in[0];
    const float* Wq = (const float*)d_in[1];
    const float* bq = (const float*)d_in[2];
    const float* Wk = (const float*)d_in[3];
    const float* bk = (const float*)d_in[4];

    float* out   = (float*)d_out;                       // [B,N,T,1]
    float* attnw = out + (size_t)B_ * N_ * T_;          // [B,N,N]

    cudaFuncSetAttribute(k_out, cudaFuncAttributeMaxDynamicSharedMemorySize, 65536);

    k_var<<<B_ * N_, 256>>>(x);
    k_attn<<<B_, 64>>>(Wq, bq, Wk, bk, attnw);
    k_out<<<dim3(T_ / 128, B_), 256, 65536>>>(x, attnw, out);
}

// round 4
// speedup vs baseline: 2.1702x; 1.5037x over previous
#include <cuda_runtime.h>
#include <cstdint>

#define B_ 256
#define N_ 64
#define T_ 4096
#define H_ 16

typedef unsigned int uint32;

__device__ float g_energy[B_ * N_];

// ---------- helpers ----------
static __device__ __forceinline__ uint32 smem_u32(const void* p) {
    uint32 a;
    asm("{ .reg .u64 t; cvta.to.shared.u64 t, %1; cvt.u32.u64 %0, t; }" : "=r"(a) : "l"(p));
    return a;
}
// pack two fp32 -> bf16x2, f0 in low 16 bits
static __device__ __forceinline__ uint32 pack_bf16x2(float f0, float f1) {
    uint32 r;
    asm("cvt.rn.bf16x2.f32 %0, %1, %2;" : "=r"(r) : "f"(f1), "f"(f0));
    return r;
}
static __device__ __forceinline__ float back_lo(uint32 u) { return __uint_as_float(u << 16); }
static __device__ __forceinline__ float back_hi(uint32 u) { return __uint_as_float(u & 0xffff0000u); }
// hi/lo split of an fp32 pair into two bf16x2 regs
static __device__ __forceinline__ void split_pair(float f0, float f1, uint32& h, uint32& l) {
    h = pack_bf16x2(f0, f1);
    l = pack_bf16x2(f0 - back_lo(h), f1 - back_hi(h));
}

#define MMA_BF16(c0, c1, c2, c3, a0, a1, a2, a3, b0, b1) \
    asm volatile("mma.sync.aligned.m16n8k16.row.col.f32.bf16.bf16.f32 " \
        "{%0,%1,%2,%3}, {%4,%5,%6,%7}, {%8,%9}, {%0,%1,%2,%3};" \
        : "+f"(c0), "+f"(c1), "+f"(c2), "+f"(c3) \
        : "r"(a0), "r"(a1), "r"(a2), "r"(a3), "r"(b0), "r"(b1))

#define LDSM_X4_T(r0, r1, r2, r3, addr) \
    asm volatile("ldmatrix.sync.aligned.m8n8.x4.trans.shared.b16 {%0,%1,%2,%3}, [%4];" \
        : "=r"(r0), "=r"(r1), "=r"(r2), "=r"(r3) : "r"(addr))

// ---------- K1: variance (at HBM roofline) ----------
__global__ void __launch_bounds__(256) k_var(const float* __restrict__ x) {
    size_t base = (size_t)blockIdx.x * T_;
    const float4* xp = (const float4*)(x + base);
    float s = 0.f, ss = 0.f;
#pragma unroll
    for (int it = 0; it < 4; it++) {
        float4 v = xp[threadIdx.x + it * 256];
        s  += (v.x + v.y) + (v.z + v.w);
        ss += (v.x * v.x + v.y * v.y) + (v.z * v.z + v.w * v.w);
    }
#pragma unroll
    for (int o = 16; o; o >>= 1) {
        s  += __shfl_xor_sync(0xffffffffu, s, o);
        ss += __shfl_xor_sync(0xffffffffu, ss, o);
    }
    __shared__ float sh_s[8], sh_ss[8];
    if ((threadIdx.x & 31) == 0) { sh_s[threadIdx.x >> 5] = s; sh_ss[threadIdx.x >> 5] = ss; }
    __syncthreads();
    if (threadIdx.x == 0) {
        float S = 0.f, SS = 0.f;
#pragma unroll
        for (int w = 0; w < 8; w++) { S += sh_s[w]; SS += sh_ss[w]; }
        float mean = S * (1.f / T_);
        g_energy[blockIdx.x] = SS * (1.f / T_) - mean * mean;
    }
}

// ---------- K2: closed-form logits + masked softmax ----------
__global__ void __launch_bounds__(64) k_attn(const float* __restrict__ Wq,
                                             const float* __restrict__ bq,
                                             const float* __restrict__ Wk,
                                             const float* __restrict__ bk,
                                             float* __restrict__ attnw) {
    int b = blockIdx.x;
    int i = threadIdx.x;
    __shared__ float es[N_];
    es[i] = g_energy[b * N_ + i];

    float cqk = 0.f, cqb = 0.f, cbk = 0.f, cbb = 0.f;
#pragma unroll
    for (int h = 0; h < H_; h++) {
        float wq = Wq[h], wk = Wk[h], vq = bq[h], vk = bk[h];
        cqk += wq * wk; cqb += wq * vk; cbk += vq * wk; cbb += vq * vk;
    }
    __syncthreads();

    const float scale = 0.25f;
    float ei = es[i];
    float l[N_];
    float m = -3.4e38f;
#pragma unroll
    for (int j = 0; j < N_; j++) {
        float ej = es[j];
        float v = scale * (cqk * ei * ej + cqb * ei + cbk * ej + cbb);
        if (j == i) v = -1e9f;
        l[j] = v;
        m = fmaxf(m, v);
    }
    float sum = 0.f;
#pragma unroll
    for (int j = 0; j < N_; j++) { float e = expf(l[j] - m); l[j] = e; sum += e; }
    float inv = 1.f / sum;
    float* outp = attnw + ((size_t)b * N_ + i) * N_;
#pragma unroll
    for (int j = 0; j < N_; j += 4) {
        float4 v = make_float4(l[j] * inv, l[j + 1] * inv, l[j + 2] * inv, l[j + 3] * inv);
        *(float4*)(outp + j) = v;
    }
}

// ---------- K3: mma.sync bf16 3-term — out[b,i,t] = x[b,i,t] + sum_j W[i,j] x[j,t] ----------
// CTA: batch b, 128-t tile, 256 threads = 8 warps = (4 i-tiles of 16) x (2 t-halves of 64).
// A (W) fragments persistent in regs (hi/lo); B (x^T) via ldmatrix.x4.trans from a
// XOR-swizzled bf16 hi/lo smem tile; residual reconstructed hi+lo from the same tile.
__global__ void __launch_bounds__(256) k_out_mma(const float* __restrict__ x,
                                                 const float* __restrict__ attnw,
                                                 float* __restrict__ out) {
    __shared__ __align__(256) uint32 sXh[64 * 64];  // 64 rows x 128 bf16 (16KB)
    __shared__ __align__(256) uint32 sXl[64 * 64];  // 16KB

    int b = blockIdx.y;
    int t_cta = blockIdx.x * 128;
    int tid = threadIdx.x;
    int lane = tid & 31;
    int wid = tid >> 5;
    int it = wid & 3;            // i-tile
    int th = wid >> 2;           // t-half
    int g = lane >> 2;           // fragment row group
    int cq = lane & 3;           // fragment col quad

    const float* xb = x + (size_t)b * (N_ * T_);
    float* ob = out + (size_t)b * (N_ * T_);

    // ---- stage x tile -> swizzled bf16 hi/lo smem ----
    {
        int j = tid >> 2, q = tid & 3;
        const float* xrow = xb + (size_t)j * T_ + t_cta;
        char* bh = (char*)sXh + j * 256;
        char* bl = (char*)sXl + j * 256;
        int sw = j & 7;
#pragma unroll
        for (int cc = 0; cc < 4; cc++) {
            int c = q + cc * 4;
            float4 a = *(const float4*)(xrow + c * 8);
            float4 d = *(const float4*)(xrow + c * 8 + 4);
            uint4 vh, vl;
            split_pair(a.x, a.y, vh.x, vl.x);
            split_pair(a.z, a.w, vh.y, vl.y);
            split_pair(d.x, d.y, vh.z, vl.z);
            split_pair(d.z, d.w, vh.w, vl.w);
            int off = (c ^ sw) << 4;
            *(uint4*)(bh + off) = vh;
            *(uint4*)(bl + off) = vl;
        }
    }

    // ---- load persistent A (W) fragments: hi/lo, 4 k-steps ----
    uint32 Ah[4][4], Al[4][4];
    {
        const float* ar = attnw + (size_t)b * (N_ * N_);
        int r0 = it * 16 + g, r1 = r0 + 8;
#pragma unroll
        for (int ks = 0; ks < 4; ks++) {
            int col = ks * 16 + 2 * cq;
            float2 p0 = *(const float2*)(ar + r0 * 64 + col);
            float2 p1 = *(const float2*)(ar + r1 * 64 + col);
            float2 p2 = *(const float2*)(ar + r0 * 64 + col + 8);
            float2 p3 = *(const float2*)(ar + r1 * 64 + col + 8);
            split_pair(p0.x, p0.y, Ah[ks][0], Al[ks][0]);
            split_pair(p1.x, p1.y, Ah[ks][1], Al[ks][1]);
            split_pair(p2.x, p2.y, Ah[ks][2], Al[ks][2]);
            split_pair(p3.x, p3.y, Ah[ks][3], Al[ks][3]);
        }
    }
    __syncthreads();

    uint32 baseXh = smem_u32(sXh);
    uint32 baseXl = smem_u32(sXl);
    // ldmatrix lane->row: kk*32 + lane
    uint32 rb0 = (uint32)lane * 256, rb1 = (uint32)(lane + 32) * 256;
    uint32 rs0 = (uint32)(lane & 7), rs1 = rs0;  // (lane+32)&7 == lane&7

    int i_r0 = it * 16 + g, i_r1 = i_r0 + 8;
    uint32 res_b0 = (uint32)i_r0 * 256 + (uint32)cq * 4;
    uint32 res_b1 = (uint32)i_r1 * 256 + (uint32)cq * 4;
    uint32 res_s0 = (uint32)(i_r0 & 7), res_s1 = (uint32)(i_r1 & 7);

#pragma unroll
    for (int chunk = 0; chunk < 8; chunk++) {
        uint32 tch = (uint32)(th * 8 + chunk);
        float c0 = 0.f, c1 = 0.f, c2 = 0.f, c3 = 0.f;
#pragma unroll
        for (int kk = 0; kk < 2; kk++) {
            uint32 rb = kk ? rb1 : rb0;
            uint32 sw = ((tch ^ (kk ? rs1 : rs0)) << 4);
            uint32 bh0, bh1, bh2, bh3, bl0, bl1, bl2, bl3;
            LDSM_X4_T(bh0, bh1, bh2, bh3, baseXh + rb + sw);
            LDSM_X4_T(bl0, bl1, bl2, bl3, baseXl + rb + sw);
            int ks = 2 * kk;
            MMA_BF16(c0, c1, c2, c3, Ah[ks][0], Ah[ks][1], Ah[ks][2], Ah[ks][3], bh0, bh1);
            MMA_BF16(c0, c1, c2, c3, Al[ks][0], Al[ks][1], Al[ks][2], Al[ks][3], bh0, bh1);
            MMA_BF16(c0, c1, c2, c3, Ah[ks][0], Ah[ks][1], Ah[ks][2], Ah[ks][3], bl0, bl1);
            MMA_BF16(c0, c1, c2, c3, Ah[ks + 1][0], Ah[ks + 1][1], Ah[ks + 1][2], Ah[ks + 1][3], bh2, bh3);
            MMA_BF16(c0, c1, c2, c3, Al[ks + 1][0], Al[ks + 1][1], Al[ks + 1][2], Al[ks + 1][3], bh2, bh3);
            MMA_BF16(c0, c1, c2, c3, Ah[ks + 1][0], Ah[ks + 1][1], Ah[ks + 1][2], Ah[ks + 1][3], bl2, bl3);
        }

        // residual from smem (hi+lo reconstruction) + store
        uint32 sw0 = (tch ^ res_s0) << 4;
        uint32 sw1 = (tch ^ res_s1) << 4;
        uint32 h0 = *(const uint32*)((char*)sXh + res_b0 + sw0);
        uint32 l0 = *(const uint32*)((char*)sXl + res_b0 + sw0);
        uint32 h1 = *(const uint32*)((char*)sXh + res_b1 + sw1);
        uint32 l1 = *(const uint32*)((char*)sXl + res_b1 + sw1);

        int tg = t_cta + th * 64 + chunk * 8 + 2 * cq;
        float2 o0 = make_float2(c0 + back_lo(h0) + back_lo(l0),
                                c1 + back_hi(h0) + back_hi(l0));
        float2 o1 = make_float2(c2 + back_lo(h1) + back_lo(l1),
                                c3 + back_hi(h1) + back_hi(l1));
        *(float2*)(ob + (size_t)i_r0 * T_ + tg) = o0;
        *(float2*)(ob + (size_t)i_r1 * T_ + tg) = o1;
    }
}

extern "C" void kernel_launch(void* const* d_in, const int* in_sizes, int n_in,
                              void* d_out, int out_size) {
    const float* x  = (const float*)d_in[0];
    const float* Wq = (const float*)d_in[1];
    const float* bq = (const float*)d_in[2];
    const float* Wk = (const float*)d_in[3];
    const float* bk = (const float*)d_in[4];

    float* out   = (float*)d_out;                 // [B,N,T,1]
    float* attnw = out + (size_t)B_ * N_ * T_;    // [B,N,N]

    k_var<<<B_ * N_, 256>>>(x);
    k_attn<<<B_, 64>>>(Wq, bq, Wk, bk, attnw);
    k_out_mma<<<dim3(T_ / 128, B_), 256>>>(x, attnw, out);
}

// round 8
// speedup vs baseline: 2.1958x; 1.0118x over previous
#include <cuda_runtime.h>
#include <cstdint>

#define B_ 256
#define N_ 64
#define T_ 4096
#define H_ 16

typedef unsigned int uint32;

__device__ float g_energy[B_ * N_];

// ---------- helpers ----------
static __device__ __forceinline__ uint32 smem_u32(const void* p) {
    uint32 a;
    asm("{ .reg .u64 t; cvta.to.shared.u64 t, %1; cvt.u32.u64 %0, t; }" : "=r"(a) : "l"(p));
    return a;
}
// pack two fp32 -> bf16x2, f0 in low 16 bits
static __device__ __forceinline__ uint32 pack_bf16x2(float f0, float f1) {
    uint32 r;
    asm("cvt.rn.bf16x2.f32 %0, %1, %2;" : "=r"(r) : "f"(f1), "f"(f0));
    return r;
}
static __device__ __forceinline__ float back_lo(uint32 u) { return __uint_as_float(u << 16); }
static __device__ __forceinline__ float back_hi(uint32 u) { return __uint_as_float(u & 0xffff0000u); }
static __device__ __forceinline__ void split_pair(float f0, float f1, uint32& h, uint32& l) {
    h = pack_bf16x2(f0, f1);
    l = pack_bf16x2(f0 - back_lo(h), f1 - back_hi(h));
}

#define MMA_BF16(c, a0, a1, a2, a3, b0, b1) \
    asm volatile("mma.sync.aligned.m16n8k16.row.col.f32.bf16.bf16.f32 " \
        "{%0,%1,%2,%3}, {%4,%5,%6,%7}, {%8,%9}, {%0,%1,%2,%3};" \
        : "+f"((c)[0]), "+f"((c)[1]), "+f"((c)[2]), "+f"((c)[3]) \
        : "r"(a0), "r"(a1), "r"(a2), "r"(a3), "r"(b0), "r"(b1))

#define LDSM_X4_T(r0, r1, r2, r3, addr) \
    asm volatile("ldmatrix.sync.aligned.m8n8.x4.trans.shared.b16 {%0,%1,%2,%3}, [%4];" \
        : "=r"(r0), "=r"(r1), "=r"(r2), "=r"(r3) : "r"(addr))

// ---------- K1: variance (at HBM roofline) ----------
__global__ void __launch_bounds__(256) k_var(const float* __restrict__ x) {
    size_t base = (size_t)blockIdx.x * T_;
    const float4* xp = (const float4*)(x + base);
    float s = 0.f, ss = 0.f;
#pragma unroll
    for (int it = 0; it < 4; it++) {
        float4 v = xp[threadIdx.x + it * 256];
        s  += (v.x + v.y) + (v.z + v.w);
        ss += (v.x * v.x + v.y * v.y) + (v.z * v.z + v.w * v.w);
    }
#pragma unroll
    for (int o = 16; o; o >>= 1) {
        s  += __shfl_xor_sync(0xffffffffu, s, o);
        ss += __shfl_xor_sync(0xffffffffu, ss, o);
    }
    __shared__ float sh_s[8], sh_ss[8];
    if ((threadIdx.x & 31) == 0) { sh_s[threadIdx.x >> 5] = s; sh_ss[threadIdx.x >> 5] = ss; }
    __syncthreads();
    if (threadIdx.x == 0) {
        float S = 0.f, SS = 0.f;
#pragma unroll
        for (int w = 0; w < 8; w++) { S += sh_s[w]; SS += sh_ss[w]; }
        float mean = S * (1.f / T_);
        g_energy[blockIdx.x] = SS * (1.f / T_) - mean * mean;
    }
}

// ---------- K2: closed-form logits + masked softmax ----------
__global__ void __launch_bounds__(64) k_attn(const float* __restrict__ Wq,
                                             const float* __restrict__ bq,
                                             const float* __restrict__ Wk,
                                             const float* __restrict__ bk,
                                             float* __restrict__ attnw) {
    int b = blockIdx.x;
    int i = threadIdx.x;
    __shared__ float es[N_];
    es[i] = g_energy[b * N_ + i];

    float cqk = 0.f, cqb = 0.f, cbk = 0.f, cbb = 0.f;
#pragma unroll
    for (int h = 0; h < H_; h++) {
        float wq = Wq[h], wk = Wk[h], vq = bq[h], vk = bk[h];
        cqk += wq * wk; cqb += wq * vk; cbk += vq * wk; cbb += vq * vk;
    }
    __syncthreads();

    const float scale = 0.25f;
    float ei = es[i];
    float l[N_];
    float m = -3.4e38f;
#pragma unroll
    for (int j = 0; j < N_; j++) {
        float ej = es[j];
        float v = scale * (cqk * ei * ej + cqb * ei + cbk * ej + cbb);
        if (j == i) v = -1e9f;
        l[j] = v;
        m = fmaxf(m, v);
    }
    float sum = 0.f;
#pragma unroll
    for (int j = 0; j < N_; j++) { float e = expf(l[j] - m); l[j] = e; sum += e; }
    float inv = 1.f / sum;
    float* outp = attnw + ((size_t)b * N_ + i) * N_;
#pragma unroll
    for (int j = 0; j < N_; j += 4) {
        float4 v = make_float4(l[j] * inv, l[j + 1] * inv, l[j + 2] * inv, l[j + 3] * inv);
        *(float4*)(outp + j) = v;
    }
}

// ---------- K3: mma.sync bf16 3-term, 256-t tile, 3 independent accum chains ----------
// out[b,i,t] = x[b,i,t] + sum_j W[i,j] x[j,t]
// CTA: batch b, 256-t tile, 256 threads = 8 warps = (4 i-tiles of 16) x (2 t-halves of 128).
// Smem: bf16 hi/lo x-tiles, 64 rows x 512B, XOR-swizzled 16B chunks for ldmatrix.
__global__ void __launch_bounds__(256, 2) k_out_mma(const float* __restrict__ x,
                                                    const float* __restrict__ attnw,
                                                    float* __restrict__ out) {
    extern __shared__ uint32 smem[];
    uint32* sXh = smem;                 // [64][128] u32 = 32KB
    uint32* sXl = smem + 64 * 128;      // 32KB

    int b = blockIdx.y;
    int t_cta = blockIdx.x * 256;
    int tid = threadIdx.x;
    int lane = tid & 31;
    int wid = tid >> 5;
    int it = wid & 3;            // i-tile
    int th = wid >> 2;           // t-half (128 t each)
    int g = lane >> 2;           // fragment row group
    int cq = lane & 3;           // fragment col quad

    const float* xb = x + (size_t)b * (N_ * T_);
    float* ob = out + (size_t)b * (N_ * T_);

    // ---- stage x tile (64 j x 256 t) -> swizzled bf16 hi/lo smem ----
    {
        int j = tid >> 2, q = tid & 3;
        const float* xrow = xb + (size_t)j * T_ + t_cta;
        char* bh = (char*)(sXh + j * 128);
        char* bl = (char*)(sXl + j * 128);
        int sw = j & 7;
#pragma unroll
        for (int cc = 0; cc < 8; cc++) {
            int c = q + cc * 4;                 // chunk 0..31 (8 t each)
            float4 a = *(const float4*)(xrow + c * 8);
            float4 d = *(const float4*)(xrow + c * 8 + 4);
            uint4 vh, vl;
            split_pair(a.x, a.y, vh.x, vl.x);
            split_pair(a.z, a.w, vh.y, vl.y);
            split_pair(d.x, d.y, vh.z, vl.z);
            split_pair(d.z, d.w, vh.w, vl.w);
            int off = (c ^ sw) << 4;
            *(uint4*)(bh + off) = vh;
            *(uint4*)(bl + off) = vl;
        }
    }

    // ---- persistent A (W) fragments: hi/lo, 4 k-steps ----
    uint32 Ah[4][4], Al[4][4];
    {
        const float* ar = attnw + (size_t)b * (N_ * N_);
        int r0 = it * 16 + g, r1 = r0 + 8;
#pragma unroll
        for (int ks = 0; ks < 4; ks++) {
            int col = ks * 16 + 2 * cq;
            float2 p0 = *(const float2*)(ar + r0 * 64 + col);
            float2 p1 = *(const float2*)(ar + r1 * 64 + col);
            float2 p2 = *(const float2*)(ar + r0 * 64 + col + 8);
            float2 p3 = *(const float2*)(ar + r1 * 64 + col + 8);
            split_pair(p0.x, p0.y, Ah[ks][0], Al[ks][0]);
            split_pair(p1.x, p1.y, Ah[ks][1], Al[ks][1]);
            split_pair(p2.x, p2.y, Ah[ks][2], Al[ks][2]);
            split_pair(p3.x, p3.y, Ah[ks][3], Al[ks][3]);
        }
    }
    __syncthreads();

    uint32 baseXh = smem_u32(sXh);
    uint32 baseXl = smem_u32(sXl);
    uint32 rb0 = (uint32)lane * 512;            // rows j=0..31
    uint32 rb1 = (uint32)(lane + 32) * 512;     // rows j=32..63
    uint32 rs = (uint32)(lane & 7);

    int i_r0 = it * 16 + g, i_r1 = i_r0 + 8;
    uint32 res_b0 = (uint32)i_r0 * 512 + (uint32)cq * 4;
    uint32 res_b1 = (uint32)i_r1 * 512 + (uint32)cq * 4;
    uint32 res_s0 = (uint32)(i_r0 & 7), res_s1 = (uint32)(i_r1 & 7);

#pragma unroll
    for (int chunk = 0; chunk < 16; chunk++) {
        uint32 tch = (uint32)(th * 16 + chunk);
        float cH[4] = {0.f, 0.f, 0.f, 0.f};
        float cA[4] = {0.f, 0.f, 0.f, 0.f};
        float cB[4] = {0.f, 0.f, 0.f, 0.f};
#pragma unroll
        for (int kk = 0; kk < 2; kk++) {
            uint32 rb = kk ? rb1 : rb0;
            uint32 sw = (tch ^ rs) << 4;
            uint32 bh0, bh1, bh2, bh3, bl0, bl1, bl2, bl3;
            LDSM_X4_T(bh0, bh1, bh2, bh3, baseXh + rb + sw);
            LDSM_X4_T(bl0, bl1, bl2, bl3, baseXl + rb + sw);
            int ks = 2 * kk;
            // 3 independent chains, depth 2 per kk
            MMA_BF16(cH, Ah[ks][0], Ah[ks][1], Ah[ks][2], Ah[ks][3], bh0, bh1);
            MMA_BF16(cA, Al[ks][0], Al[ks][1], Al[ks][2], Al[ks][3], bh0, bh1);
            MMA_BF16(cB, Ah[ks][0], Ah[ks][1], Ah[ks][2], Ah[ks][3], bl0, bl1);
            MMA_BF16(cH, Ah[ks + 1][0], Ah[ks + 1][1], Ah[ks + 1][2], Ah[ks + 1][3], bh2, bh3);
            MMA_BF16(cA, Al[ks + 1][0], Al[ks + 1][1], Al[ks + 1][2], Al[ks + 1][3], bh2, bh3);
            MMA_BF16(cB, Ah[ks + 1][0], Ah[ks + 1][1], Ah[ks + 1][2], Ah[ks + 1][3], bl2, bl3);
        }

        // residual from smem (hi+lo) + store
        uint32 sw0 = (tch ^ res_s0) << 4;
        uint32 sw1 = (tch ^ res_s1) << 4;
        uint32 h0 = *(const uint32*)((char*)sXh + res_b0 + sw0);
        uint32 l0 = *(const uint32*)((char*)sXl + res_b0 + sw0);
        uint32 h1 = *(const uint32*)((char*)sXh + res_b1 + sw1);
        uint32 l1 = *(const uint32*)((char*)sXl + res_b1 + sw1);

        int tg = t_cta + (int)tch * 8 + 2 * cq;
        float2 o0 = make_float2(cH[0] + cA[0] + cB[0] + back_lo(h0) + back_lo(l0),
                                cH[1] + cA[1] + cB[1] + back_hi(h0) + back_hi(l0));
        float2 o1 = make_float2(cH[2] + cA[2] + cB[2] + back_lo(h1) + back_lo(l1),
                                cH[3] + cA[3] + cB[3] + back_hi(h1) + back_hi(l1));
        *(float2*)(ob + (size_t)i_r0 * T_ + tg) = o0;
        *(float2*)(ob + (size_t)i_r1 * T_ + tg) = o1;
    }
}

extern "C" void kernel_launch(void* const* d_in, const int* in_sizes, int n_in,
                              void* d_out, int out_size) {
    const float* x  = (const float*)d_in[0];
    const float* Wq = (const float*)d_in[1];
    const float* bq = (const float*)d_in[2];
    const float* Wk = (const float*)d_in[3];
    const float* bk = (const float*)d_in[4];

    float* out   = (float*)d_out;                 // [B,N,T,1]
    float* attnw = out + (size_t)B_ * N_ * T_;    // [B,N,N]

    cudaFuncSetAttribute(k_out_mma, cudaFuncAttributeMaxDynamicSharedMemorySize, 65536);

    k_var<<<B_ * N_, 256>>>(x);
    k_attn<<<B_, 64>>>(Wq, bq, Wk, bk, attnw);
    k_out_mma<<<dim3(T_ / 256, B_), 256, 65536>>>(x, attnw, out);
}

// round 9
// speedup vs baseline: 2.4270x; 1.1053x over previous
#include <cuda_runtime.h>
#include <cuda_fp16.h>
#include <cstdint>

#define B_ 256
#define N_ 64
#define T_ 4096
#define H_ 16

typedef unsigned int uint32;

__device__ float g_energy[B_ * N_];

// ---------- helpers ----------
static __device__ __forceinline__ uint32 smem_u32(const void* p) {
    uint32 a;
    asm("{ .reg .u64 t; cvta.to.shared.u64 t, %1; cvt.u32.u64 %0, t; }" : "=r"(a) : "l"(p));
    return a;
}
// pack two fp32 -> f16x2, f0 in low 16 bits
static __device__ __forceinline__ uint32 pack_f16x2(float f0, float f1) {
    uint32 r;
    asm("cvt.rn.f16x2.f32 %0, %1, %2;" : "=r"(r) : "f"(f1), "f"(f0));
    return r;
}
static __device__ __forceinline__ float2 h2f2(uint32 u) {
    __half2 h = *(__half2*)&u;
    return __half22float2(h);
}
// fp16 hi/lo split of an fp32 pair (lo captures hi rounding error; x ~= h + l to 2^-24)
static __device__ __forceinline__ void split_pair_f16(float f0, float f1, uint32& h, uint32& l) {
    h = pack_f16x2(f0, f1);
    float2 b = h2f2(h);
    l = pack_f16x2(f0 - b.x, f1 - b.y);
}

#define MMA_F16(c, a0, a1, a2, a3, b0, b1) \
    asm volatile("mma.sync.aligned.m16n8k16.row.col.f32.f16.f16.f32 " \
        "{%0,%1,%2,%3}, {%4,%5,%6,%7}, {%8,%9}, {%0,%1,%2,%3};" \
        : "+f"((c)[0]), "+f"((c)[1]), "+f"((c)[2]), "+f"((c)[3]) \
        : "r"(a0), "r"(a1), "r"(a2), "r"(a3), "r"(b0), "r"(b1))

#define LDSM_X4_T(r0, r1, r2, r3, addr) \
    asm volatile("ldmatrix.sync.aligned.m8n8.x4.trans.shared.b16 {%0,%1,%2,%3}, [%4];" \
        : "=r"(r0), "=r"(r1), "=r"(r2), "=r"(r3) : "r"(addr))

// ---------- K1: variance (at HBM roofline) ----------
__global__ void __launch_bounds__(256) k_var(const float* __restrict__ x) {
    size_t base = (size_t)blockIdx.x * T_;
    const float4* xp = (const float4*)(x + base);
    float s = 0.f, ss = 0.f;
#pragma unroll
    for (int it = 0; it < 4; it++) {
        float4 v = xp[threadIdx.x + it * 256];
        s  += (v.x + v.y) + (v.z + v.w);
        ss += (v.x * v.x + v.y * v.y) + (v.z * v.z + v.w * v.w);
    }
#pragma unroll
    for (int o = 16; o; o >>= 1) {
        s  += __shfl_xor_sync(0xffffffffu, s, o);
        ss += __shfl_xor_sync(0xffffffffu, ss, o);
    }
    __shared__ float sh_s[8], sh_ss[8];
    if ((threadIdx.x & 31) == 0) { sh_s[threadIdx.x >> 5] = s; sh_ss[threadIdx.x >> 5] = ss; }
    __syncthreads();
    if (threadIdx.x == 0) {
        float S = 0.f, SS = 0.f;
#pragma unroll
        for (int w = 0; w < 8; w++) { S += sh_s[w]; SS += sh_ss[w]; }
        float mean = S * (1.f / T_);
        g_energy[blockIdx.x] = SS * (1.f / T_) - mean * mean;
    }
}

// ---------- K2: closed-form logits + masked softmax ----------
__global__ void __launch_bounds__(64) k_attn(const float* __restrict__ Wq,
                                             const float* __restrict__ bq,
                                             const float* __restrict__ Wk,
                                             const float* __restrict__ bk,
                                             float* __restrict__ attnw) {
    int b = blockIdx.x;
    int i = threadIdx.x;
    __shared__ float es[N_];
    es[i] = g_energy[b * N_ + i];

    float cqk = 0.f, cqb = 0.f, cbk = 0.f, cbb = 0.f;
#pragma unroll
    for (int h = 0; h < H_; h++) {
        float wq = Wq[h], wk = Wk[h], vq = bq[h], vk = bk[h];
        cqk += wq * wk; cqb += wq * vk; cbk += vq * wk; cbb += vq * vk;
    }
    __syncthreads();

    const float scale = 0.25f;
    float ei = es[i];
    float l[N_];
    float m = -3.4e38f;
#pragma unroll
    for (int j = 0; j < N_; j++) {
        float ej = es[j];
        float v = scale * (cqk * ei * ej + cqb * ei + cbk * ej + cbb);
        if (j == i) v = -1e9f;
        l[j] = v;
        m = fmaxf(m, v);
    }
    float sum = 0.f;
#pragma unroll
    for (int j = 0; j < N_; j++) { float e = expf(l[j] - m); l[j] = e; sum += e; }
    float inv = 1.f / sum;
    float* outp = attnw + ((size_t)b * N_ + i) * N_;
#pragma unroll
    for (int j = 0; j < N_; j += 4) {
        float4 v = make_float4(l[j] * inv, l[j + 1] * inv, l[j + 2] * inv, l[j + 3] * inv);
        *(float4*)(outp + j) = v;
    }
}

// ---------- K3: single-term fp16 mma.sync — out[b,i,t] = x[b,i,t] + sum_j W[i,j] x[j,t] ----------
// CTA: batch b, 256-t tile, 256 threads = 8 warps = (4 i-tiles of 16) x (2 t-halves of 128).
// MMA uses only Xh (fp16-hi); Xl is kept solely for exact residual reconstruction
// (x = h + l to 2^-24). W fp16 single. 4 MMAs/chunk (was 12), half the LDSM traffic.
__global__ void __launch_bounds__(256, 2) k_out_mma(const float* __restrict__ x,
                                                    const float* __restrict__ attnw,
                                                    float* __restrict__ out) {
    extern __shared__ uint32 smem[];
    uint32* sXh = smem;                 // [64][128] u32 (f16x2) = 32KB, MMA + residual
    uint32* sXl = smem + 64 * 128;      // 32KB, residual only

    int b = blockIdx.y;
    int t_cta = blockIdx.x * 256;
    int tid = threadIdx.x;
    int lane = tid & 31;
    int wid = tid >> 5;
    int it = wid & 3;            // i-tile
    int th = wid >> 2;           // t-half (128 t each)
    int g = lane >> 2;           // fragment row group
    int cq = lane & 3;           // fragment col quad

    const float* xb = x + (size_t)b * (N_ * T_);
    float* ob = out + (size_t)b * (N_ * T_);

    // ---- stage x tile (64 j x 256 t) -> swizzled fp16 hi/lo smem ----
    {
        int j = tid >> 2, q = tid & 3;
        const float* xrow = xb + (size_t)j * T_ + t_cta;
        char* bh = (char*)(sXh + j * 128);
        char* bl = (char*)(sXl + j * 128);
        int sw = j & 7;
#pragma unroll
        for (int cc = 0; cc < 8; cc++) {
            int c = q + cc * 4;                 // chunk 0..31 (8 t each)
            float4 a = *(const float4*)(xrow + c * 8);
            float4 d = *(const float4*)(xrow + c * 8 + 4);
            uint4 vh, vl;
            split_pair_f16(a.x, a.y, vh.x, vl.x);
            split_pair_f16(a.z, a.w, vh.y, vl.y);
            split_pair_f16(d.x, d.y, vh.z, vl.z);
            split_pair_f16(d.z, d.w, vh.w, vl.w);
            int off = (c ^ sw) << 4;
            *(uint4*)(bh + off) = vh;
            *(uint4*)(bl + off) = vl;
        }
    }

    // ---- persistent A (W) fragments: single fp16, 4 k-steps ----
    uint32 Wf[4][4];
    {
        const float* ar = attnw + (size_t)b * (N_ * N_);
        int r0 = it * 16 + g, r1 = r0 + 8;
#pragma unroll
        for (int ks = 0; ks < 4; ks++) {
            int col = ks * 16 + 2 * cq;
            float2 p0 = *(const float2*)(ar + r0 * 64 + col);
            float2 p1 = *(const float2*)(ar + r1 * 64 + col);
            float2 p2 = *(const float2*)(ar + r0 * 64 + col + 8);
            float2 p3 = *(const float2*)(ar + r1 * 64 + col + 8);
            Wf[ks][0] = pack_f16x2(p0.x, p0.y);
            Wf[ks][1] = pack_f16x2(p1.x, p1.y);
            Wf[ks][2] = pack_f16x2(p2.x, p2.y);
            Wf[ks][3] = pack_f16x2(p3.x, p3.y);
        }
    }
    __syncthreads();

    uint32 baseXh = smem_u32(sXh);
    uint32 rb0 = (uint32)lane * 512;            // rows j=0..31
    uint32 rb1 = (uint32)(lane + 32) * 512;     // rows j=32..63
    uint32 rs = (uint32)(lane & 7);

    int i_r0 = it * 16 + g, i_r1 = i_r0 + 8;
    uint32 res_b0 = (uint32)i_r0 * 512 + (uint32)cq * 4;
    uint32 res_b1 = (uint32)i_r1 * 512 + (uint32)cq * 4;
    uint32 res_s0 = (uint32)(i_r0 & 7), res_s1 = (uint32)(i_r1 & 7);

#pragma unroll
    for (int chunk = 0; chunk < 16; chunk++) {
        uint32 tch = (uint32)(th * 16 + chunk);
        float acc[4] = {0.f, 0.f, 0.f, 0.f};
        uint32 sw = (tch ^ rs) << 4;
        {
            uint32 b0, b1, b2, b3;
            LDSM_X4_T(b0, b1, b2, b3, baseXh + rb0 + sw);      // rows 0..31
            MMA_F16(acc, Wf[0][0], Wf[0][1], Wf[0][2], Wf[0][3], b0, b1);
            MMA_F16(acc, Wf[1][0], Wf[1][1], Wf[1][2], Wf[1][3], b2, b3);
        }
        {
            uint32 b0, b1, b2, b3;
            LDSM_X4_T(b0, b1, b2, b3, baseXh + rb1 + sw);      // rows 32..63
            MMA_F16(acc, Wf[2][0], Wf[2][1], Wf[2][2], Wf[2][3], b0, b1);
            MMA_F16(acc, Wf[3][0], Wf[3][1], Wf[3][2], Wf[3][3], b2, b3);
        }

        // exact residual from smem (h + l) + store
        uint32 sw0 = (tch ^ res_s0) << 4;
        uint32 sw1 = (tch ^ res_s1) << 4;
        uint32 h0 = *(const uint32*)((char*)sXh + res_b0 + sw0);
        uint32 l0 = *(const uint32*)((char*)sXl + res_b0 + sw0);
        uint32 h1 = *(const uint32*)((char*)sXh + res_b1 + sw1);
        uint32 l1 = *(const uint32*)((char*)sXl + res_b1 + sw1);
        float2 xh0 = h2f2(h0), xl0 = h2f2(l0);
        float2 xh1 = h2f2(h1), xl1 = h2f2(l1);

        int tg = t_cta + (int)tch * 8 + 2 * cq;
        float2 o0 = make_float2(acc[0] + xh0.x + xl0.x, acc[1] + xh0.y + xl0.y);
        float2 o1 = make_float2(acc[2] + xh1.x + xl1.x, acc[3] + xh1.y + xl1.y);
        *(float2*)(ob + (size_t)i_r0 * T_ + tg) = o0;
        *(float2*)(ob + (size_t)i_r1 * T_ + tg) = o1;
    }
}

extern "C" void kernel_launch(void* const* d_in, const int* in_sizes, int n_in,
                              void* d_out, int out_size) {
    const float* x  = (const float*)d_in[0];
    const float* Wq = (const float*)d_in[1];
    const float* bq = (const float*)d_in[2];
    const float* Wk = (const float*)d_in[3];
    const float* bk = (const float*)d_in[4];

    float* out   = (float*)d_out;                 // [B,N,T,1]
    float* attnw = out + (size_t)B_ * N_ * T_;    // [B,N,N]

    cudaFuncSetAttribute(k_out_mma, cudaFuncAttributeMaxDynamicSharedMemorySize, 65536);

    k_var<<<B_ * N_, 256>>>(x);
    k_attn<<<B_, 64>>>(Wq, bq, Wk, bk, attnw);
    k_out_mma<<<dim3(T_ / 256, B_), 256, 65536>>>(x, attnw, out);
}